// round 10
// baseline (speedup 1.0000x reference)
#include <cuda_runtime.h>
#include <cuda_fp16.h>
#include <math.h>

#define D       128
#define NMAX    100000
#define EMAX    1600000
#define NGRAPH  64
#define NEG_SLOPE 0.2f
#define AS      136   // smem row stride in halves (128 + 8 pad)
#define FULL    0xffffffffu

typedef unsigned int  u32;
typedef unsigned long long u64;

// ---------------- scratch (static device globals; no allocation) ------------
__device__ __half g_bufH[(size_t)NMAX * D];  // layer feat fp16 (25.6 MB)
__device__ __half g_bufB[(size_t)NMAX * D];  // agg output fp16 (25.6 MB)
__device__ float  g_el[NMAX];
__device__ float  g_er[NMAX];
__device__ float  g_e[EMAX];                 // per-edge scratch (deg>32 path)
__device__ int    g_cnt[NMAX];
__device__ int    g_rowptr[NMAX + 1];
__device__ int    g_cursor[NMAX];
__device__ int    g_col[EMAX];               // src ids sorted by dst
__device__ float  g_acc[NGRAPH * 2];
__device__ float  g_gcnt[NGRAPH];

// ================= CSR build =================
__global__ void hist_kernel(const int* __restrict__ dst, int* __restrict__ cnt, int E) {
    int i = blockIdx.x * blockDim.x + threadIdx.x;
    if (i < E) atomicAdd(&cnt[dst[i]], 1);
}

__global__ void scan_kernel(const int* __restrict__ cnt, int* __restrict__ rowptr,
                            int* __restrict__ cursor, int N) {
    __shared__ int wsum[32];
    int t = threadIdx.x;
    int chunk = (N + 1023) >> 10;
    int b = t * chunk; if (b > N) b = N;
    int e = b + chunk; if (e > N) e = N;
    int sum = 0;
    for (int i = b; i < e; i++) sum += cnt[i];
    int lane = t & 31, w = t >> 5;
    int v = sum;
#pragma unroll
    for (int o = 1; o < 32; o <<= 1) {
        int u = __shfl_up_sync(FULL, v, o);
        if (lane >= o) v += u;
    }
    if (lane == 31) wsum[w] = v;
    __syncthreads();
    if (w == 0) {
        int x = wsum[lane];
#pragma unroll
        for (int o = 1; o < 32; o <<= 1) {
            int u = __shfl_up_sync(FULL, x, o);
            if (lane >= o) x += u;
        }
        wsum[lane] = x;
    }
    __syncthreads();
    int run = v - sum + (w > 0 ? wsum[w - 1] : 0);
    for (int i = b; i < e; i++) {
        rowptr[i] = run; cursor[i] = run;
        run += cnt[i];
    }
    if (b < N && e == N) rowptr[N] = run;
}

__global__ void scatter_kernel(const int* __restrict__ src, const int* __restrict__ dst,
                               int* __restrict__ cursor, int* __restrict__ col, int E) {
    int i = blockIdx.x * blockDim.x + threadIdx.x;
    if (i < E) {
        int p = atomicAdd(&cursor[dst[i]], 1);
        col[p] = src[i];
    }
}

// ====== HMMA GEMM: outH = half(act(X) @ W); fused el/er epilogue ============
#define GEMM_SMEM (2 * 128 * AS * 2 + 2 * 4 * 128 * 4)

__global__ void __launch_bounds__(512, 1)
gemm_hmma_kernel(const float* __restrict__ Xf, const __half* __restrict__ Xh,
                 const float* __restrict__ W,
                 const float* __restrict__ preBias, int preRelu,
                 const float* __restrict__ al, const float* __restrict__ ar,
                 __half* __restrict__ outH, float* __restrict__ el,
                 float* __restrict__ er, int N) {
    extern __shared__ char smraw[];
    __half* As = (__half*)smraw;                    // [128][AS]
    __half* Bs = As + 128 * AS;                     // [128][AS]
    float* redEl = (float*)(Bs + 128 * AS);         // [4][128]
    float* redEr = redEl + 4 * 128;                 // [4][128]

    const int tx   = threadIdx.x;
    const int lane = tx & 31;
    const int warp = tx >> 5;
    const int row0 = blockIdx.x * 128;

    // ---- stage W -> Bs (fp32 -> fp16) ----
    {
        int k  = tx >> 2;
        int n0 = (tx & 3) * 32;
        const float* wr_ = W + k * D + n0;
#pragma unroll
        for (int j = 0; j < 32; j += 8) {
            float4 v0 = *(const float4*)&wr_[j];
            float4 v1 = *(const float4*)&wr_[j + 4];
            __half2 h0 = __floats2half2_rn(v0.x, v0.y);
            __half2 h1 = __floats2half2_rn(v0.z, v0.w);
            __half2 h2 = __floats2half2_rn(v1.x, v1.y);
            __half2 h3 = __floats2half2_rn(v1.z, v1.w);
            uint4 u = make_uint4(*(u32*)&h0, *(u32*)&h1, *(u32*)&h2, *(u32*)&h3);
            *(uint4*)&Bs[k * AS + n0 + j] = u;
        }
    }

    // ---- stage X -> As ----
    {
        int r    = tx >> 2;
        int c0   = (tx & 3) * 32;
        int grow = row0 + r;
        if (grow < N) {
            if (Xf) {
                const float* xr_ = Xf + (size_t)grow * D + c0;
#pragma unroll
                for (int j = 0; j < 32; j += 8) {
                    float4 v0 = *(const float4*)&xr_[j];
                    float4 v1 = *(const float4*)&xr_[j + 4];
                    __half2 h0 = __floats2half2_rn(v0.x, v0.y);
                    __half2 h1 = __floats2half2_rn(v0.z, v0.w);
                    __half2 h2 = __floats2half2_rn(v1.x, v1.y);
                    __half2 h3 = __floats2half2_rn(v1.z, v1.w);
                    uint4 u = make_uint4(*(u32*)&h0, *(u32*)&h1, *(u32*)&h2, *(u32*)&h3);
                    *(uint4*)&As[r * AS + c0 + j] = u;
                }
            } else {
                const __half* xr_ = Xh + (size_t)grow * D + c0;
#pragma unroll
                for (int j = 0; j < 32; j += 8) {
                    uint4 raw = *(const uint4*)&xr_[j];
                    if (preRelu) {
                        const float* bb = preBias + c0 + j;
                        float2 f0 = __half22float2(*(__half2*)&raw.x);
                        float2 f1 = __half22float2(*(__half2*)&raw.y);
                        float2 f2 = __half22float2(*(__half2*)&raw.z);
                        float2 f3 = __half22float2(*(__half2*)&raw.w);
                        f0.x = fmaxf(f0.x + bb[0], 0.f); f0.y = fmaxf(f0.y + bb[1], 0.f);
                        f1.x = fmaxf(f1.x + bb[2], 0.f); f1.y = fmaxf(f1.y + bb[3], 0.f);
                        f2.x = fmaxf(f2.x + bb[4], 0.f); f2.y = fmaxf(f2.y + bb[5], 0.f);
                        f3.x = fmaxf(f3.x + bb[6], 0.f); f3.y = fmaxf(f3.y + bb[7], 0.f);
                        __half2 h0 = __floats2half2_rn(f0.x, f0.y);
                        __half2 h1 = __floats2half2_rn(f1.x, f1.y);
                        __half2 h2 = __floats2half2_rn(f2.x, f2.y);
                        __half2 h3 = __floats2half2_rn(f3.x, f3.y);
                        raw = make_uint4(*(u32*)&h0, *(u32*)&h1, *(u32*)&h2, *(u32*)&h3);
                    }
                    *(uint4*)&As[r * AS + c0 + j] = raw;
                }
            }
        } else {
#pragma unroll
            for (int j = 0; j < 32; j += 8)
                *(uint4*)&As[r * AS + c0 + j] = make_uint4(0, 0, 0, 0);
        }
    }
    __syncthreads();

    // ---- mainloop ----
    const int wr = warp >> 2;
    const int wc = warp & 3;
    float acc[2][4][4];
#pragma unroll
    for (int a = 0; a < 2; a++)
#pragma unroll
        for (int n = 0; n < 4; n++)
#pragma unroll
            for (int i = 0; i < 4; i++) acc[a][n][i] = 0.f;

    const u32 as_base = (u32)__cvta_generic_to_shared(As);
    const u32 bs_base = (u32)__cvta_generic_to_shared(Bs);
    const int g  = lane >> 3;
    const int gi = lane & 7;

#pragma unroll
    for (int ks = 0; ks < 8; ks++) {
        const int k0 = ks * 16;
        u32 afr[2][4];
#pragma unroll
        for (int at = 0; at < 2; at++) {
            int arow = wr * 32 + at * 16 + gi + (g & 1) * 8;
            int acol = k0 + (g >> 1) * 8;
            u32 addr = as_base + (arow * AS + acol) * 2;
            asm volatile("ldmatrix.sync.aligned.m8n8.x4.shared.b16 {%0,%1,%2,%3}, [%4];"
                         : "=r"(afr[at][0]), "=r"(afr[at][1]),
                           "=r"(afr[at][2]), "=r"(afr[at][3]) : "r"(addr));
        }
        u32 bfr[4][2];
#pragma unroll
        for (int h = 0; h < 2; h++) {
            int krow = k0 + gi + (g & 1) * 8;
            int ncol = wc * 32 + h * 16 + (g >> 1) * 8;
            u32 addr = bs_base + (krow * AS + ncol) * 2;
            u32 r0, r1, r2, r3;
            asm volatile("ldmatrix.sync.aligned.m8n8.x4.trans.shared.b16 {%0,%1,%2,%3}, [%4];"
                         : "=r"(r0), "=r"(r1), "=r"(r2), "=r"(r3) : "r"(addr));
            bfr[h * 2][0] = r0;     bfr[h * 2][1] = r1;
            bfr[h * 2 + 1][0] = r2; bfr[h * 2 + 1][1] = r3;
        }
#pragma unroll
        for (int at = 0; at < 2; at++)
#pragma unroll
            for (int nt = 0; nt < 4; nt++) {
                asm volatile(
                    "mma.sync.aligned.m16n8k16.row.col.f32.f16.f16.f32 "
                    "{%0,%1,%2,%3}, {%4,%5,%6,%7}, {%8,%9}, {%0,%1,%2,%3};"
                    : "+f"(acc[at][nt][0]), "+f"(acc[at][nt][1]),
                      "+f"(acc[at][nt][2]), "+f"(acc[at][nt][3])
                    : "r"(afr[at][0]), "r"(afr[at][1]), "r"(afr[at][2]), "r"(afr[at][3]),
                      "r"(bfr[nt][0]), "r"(bfr[nt][1]));
            }
    }

    // ---- epilogue ----
#pragma unroll
    for (int at = 0; at < 2; at++) {
        int r_lo = wr * 32 + at * 16 + (lane >> 2);
        int r_hi = r_lo + 8;
        float pll = 0.f, prl = 0.f, plh = 0.f, prh = 0.f;
#pragma unroll
        for (int nt = 0; nt < 4; nt++) {
            int colc = wc * 32 + nt * 8 + 2 * (lane & 3);
            float c0 = acc[at][nt][0], c1 = acc[at][nt][1];
            float c2 = acc[at][nt][2], c3 = acc[at][nt][3];
            float a0 = al[colc], a1 = al[colc + 1];
            float b0 = ar[colc], b1 = ar[colc + 1];
            pll += c0 * a0 + c1 * a1;  prl += c0 * b0 + c1 * b1;
            plh += c2 * a0 + c3 * a1;  prh += c2 * b0 + c3 * b1;
            if (row0 + r_lo < N) {
                __half2 h = __floats2half2_rn(c0, c1);
                *(__half2*)&outH[(size_t)(row0 + r_lo) * D + colc] = h;
            }
            if (row0 + r_hi < N) {
                __half2 h = __floats2half2_rn(c2, c3);
                *(__half2*)&outH[(size_t)(row0 + r_hi) * D + colc] = h;
            }
        }
#pragma unroll
        for (int o = 1; o <= 2; o <<= 1) {
            pll += __shfl_xor_sync(FULL, pll, o);
            prl += __shfl_xor_sync(FULL, prl, o);
            plh += __shfl_xor_sync(FULL, plh, o);
            prh += __shfl_xor_sync(FULL, prh, o);
        }
        if ((lane & 3) == 0) {
            redEl[wc * 128 + r_lo] = pll;  redEr[wc * 128 + r_lo] = prl;
            redEl[wc * 128 + r_hi] = plh;  redEr[wc * 128 + r_hi] = prh;
        }
    }
    __syncthreads();
    if (tx < 128 && row0 + tx < N) {
        float sl = redEl[tx] + redEl[128 + tx] + redEl[256 + tx] + redEl[384 + tx];
        float sr = redEr[tx] + redEr[128 + tx] + redEr[256 + tx] + redEr[384 + tx];
        el[row0 + tx] = sl;
        er[row0 + tx] = sr;
    }
}

// ========== fused per-dst edge softmax + aggregation (warp per dst) =========
// Gather phase: 16 lanes per edge (LDG.128, 16B/lane), 2 edges per warp-step,
// up to 16 edges in flight. Lane l accumulates features (l&15)*8 .. +8.
__device__ __forceinline__ void fma_half16(float* a, float w, uint4 u) {
    float2 f0 = __half22float2(*reinterpret_cast<__half2*>(&u.x));
    float2 f1 = __half22float2(*reinterpret_cast<__half2*>(&u.y));
    float2 f2 = __half22float2(*reinterpret_cast<__half2*>(&u.z));
    float2 f3 = __half22float2(*reinterpret_cast<__half2*>(&u.w));
    a[0] = fmaf(w, f0.x, a[0]); a[1] = fmaf(w, f0.y, a[1]);
    a[2] = fmaf(w, f1.x, a[2]); a[3] = fmaf(w, f1.y, a[3]);
    a[4] = fmaf(w, f2.x, a[4]); a[5] = fmaf(w, f2.y, a[5]);
    a[6] = fmaf(w, f3.x, a[6]); a[7] = fmaf(w, f3.y, a[7]);
}

// gather over edges [0,cnt) given per-lane edge data (idx, weight already *inv)
__device__ __forceinline__ void gather_pairs(float* a, int myi, float myw, int cnt,
                                             const __half* __restrict__ feat,
                                             int half, int hl) {
    int j = 0;
    for (; j + 15 < cnt; j += 16) {
        int sv[8]; float wv[8]; uint4 u[8];
#pragma unroll
        for (int t = 0; t < 8; t++) {
            int e = j + 2 * t + half;
            sv[t] = __shfl_sync(FULL, myi, e);
            wv[t] = __shfl_sync(FULL, myw, e);
        }
#pragma unroll
        for (int t = 0; t < 8; t++)
            u[t] = *(const uint4*)(feat + (size_t)sv[t] * D + hl * 8);
#pragma unroll
        for (int t = 0; t < 8; t++)
            fma_half16(a, wv[t], u[t]);
    }
    for (; j + 1 < cnt; j += 2) {
        int e = j + half;
        int   s = __shfl_sync(FULL, myi, e);
        float w = __shfl_sync(FULL, myw, e);
        uint4 u = *(const uint4*)(feat + (size_t)s * D + hl * 8);
        fma_half16(a, w, u);
    }
    if (j < cnt) {   // last single edge: both halves load it, upper half weight 0
        int   s = __shfl_sync(FULL, myi, j);
        float w = __shfl_sync(FULL, myw, j);
        if (half) w = 0.f;
        uint4 u = *(const uint4*)(feat + (size_t)s * D + hl * 8);
        fma_half16(a, w, u);
    }
}

__global__ void agg_kernel(const int* __restrict__ rowptr, const int* __restrict__ col,
                           const float* __restrict__ el, const float* __restrict__ er,
                           const __half* __restrict__ feat, float* __restrict__ ebuf,
                           __half* __restrict__ out, int N, int doPool,
                           const float* __restrict__ b2, const float* __restrict__ Wfc,
                           const int* __restrict__ gid,
                           float* __restrict__ acc, float* __restrict__ gcnt) {
    int node = (blockIdx.x * blockDim.x + threadIdx.x) >> 5;
    int lane = threadIdx.x & 31;
    if (node >= N) return;
    const int half = lane >> 4;
    const int hl   = lane & 15;
    int beg = rowptr[node], end = rowptr[node + 1];
    int deg = end - beg;
    float a[8];
#pragma unroll
    for (int t = 0; t < 8; t++) a[t] = 0.f;

    if (deg > 0) {
        float erd = er[node];
        if (deg <= 32) {
            // 32-lane softmax over edges
            int   myi = 0;
            float v = -INFINITY;
            if (lane < deg) {
                myi = col[beg + lane];
                float t = el[myi] + erd;
                v = t > 0.f ? t : NEG_SLOPE * t;
            }
            float mx = v;
#pragma unroll
            for (int o = 16; o; o >>= 1)
                mx = fmaxf(mx, __shfl_xor_sync(FULL, mx, o));
            float mye = (lane < deg) ? __expf(v - mx) : 0.f;
            float s = mye;
#pragma unroll
            for (int o = 16; o; o >>= 1)
                s += __shfl_xor_sync(FULL, s, o);
            float myw = mye * (1.0f / s);
            gather_pairs(a, myi, myw, deg, feat, half, hl);
        } else {
            // general path via ebuf
            float mx = -INFINITY;
            for (int i = beg + lane; i < end; i += 32) {
                float v = el[col[i]] + erd;
                v = v > 0.f ? v : NEG_SLOPE * v;
                ebuf[i] = v;
                mx = fmaxf(mx, v);
            }
#pragma unroll
            for (int o = 16; o; o >>= 1)
                mx = fmaxf(mx, __shfl_xor_sync(FULL, mx, o));
            float s = 0.f;
            for (int i = beg + lane; i < end; i += 32) {
                float ex = __expf(ebuf[i] - mx);
                ebuf[i] = ex;
                s += ex;
            }
#pragma unroll
            for (int o = 16; o; o >>= 1)
                s += __shfl_xor_sync(FULL, s, o);
            float inv = 1.0f / s;
            for (int base = beg; base < end; base += 32) {
                int rem = end - base;
                int cnt = rem < 32 ? rem : 32;
                int mi = 0; float mw = 0.f;
                if (lane < cnt) {
                    mi = col[base + lane];
                    mw = ebuf[base + lane] * inv;
                }
                gather_pairs(a, mi, mw, cnt, feat, half, hl);
            }
        }
    }

    // combine the two half-warps (both end with the full sum)
#pragma unroll
    for (int t = 0; t < 8; t++)
        a[t] += __shfl_xor_sync(FULL, a[t], 16);

    if (!doPool) {
        if (half == 0) {
            __half2 h0 = __floats2half2_rn(a[0], a[1]);
            __half2 h1 = __floats2half2_rn(a[2], a[3]);
            __half2 h2 = __floats2half2_rn(a[4], a[5]);
            __half2 h3 = __floats2half2_rn(a[6], a[7]);
            uint4 u = make_uint4(*(u32*)&h0, *(u32*)&h1, *(u32*)&h2, *(u32*)&h3);
            *(uint4*)&out[(size_t)node * D + hl * 8] = u;
        }
    } else {
        // pool: relu(a + b2) . Wfc  (features hl*8 .. hl*8+7)
        float d0 = 0.f, d1 = 0.f;
        const float* bb = b2 + hl * 8;
        const float* wf = Wfc + hl * 16;   // [128,2] row-major
#pragma unroll
        for (int t = 0; t < 8; t++) {
            float x = fmaxf(a[t] + bb[t], 0.f);
            d0 = fmaf(x, wf[2 * t], d0);
            d1 = fmaf(x, wf[2 * t + 1], d1);
        }
#pragma unroll
        for (int o = 1; o <= 8; o <<= 1) {
            d0 += __shfl_xor_sync(FULL, d0, o);
            d1 += __shfl_xor_sync(FULL, d1, o);
        }
        if (lane == 0) {
            int g = gid[node];
            atomicAdd(&acc[g * 2 + 0], d0);
            atomicAdd(&acc[g * 2 + 1], d1);
            atomicAdd(&gcnt[g], 1.f);
        }
    }
}

// ========== finalize: mean, +bfc, log_softmax ==========
__global__ void finalize_kernel(const float* __restrict__ acc,
                                const float* __restrict__ cnt,
                                const float* __restrict__ bfc,
                                float* __restrict__ out) {
    int g = threadIdx.x;
    if (g >= NGRAPH) return;
    float c  = fmaxf(cnt[g], 1.f);
    float l0 = acc[g * 2 + 0] / c + bfc[0];
    float l1 = acc[g * 2 + 1] / c + bfc[1];
    float mx  = fmaxf(l0, l1);
    float lse = mx + logf(expf(l0 - mx) + expf(l1 - mx));
    out[g * 2 + 0] = l0 - lse;
    out[g * 2 + 1] = l1 - lse;
}

// ================= launch =================
extern "C" void kernel_launch(void* const* d_in, const int* in_sizes, int n_in,
                              void* d_out, int out_size) {
    const float* h   = (const float*)d_in[0];
    const int*   src = (const int*)d_in[1];
    const int*   dst = (const int*)d_in[2];
    const int*   gid = (const int*)d_in[3];
    const float* W1  = (const float*)d_in[4];
    const float* al1 = (const float*)d_in[5];
    const float* ar1 = (const float*)d_in[6];
    const float* b1  = (const float*)d_in[7];
    const float* W2  = (const float*)d_in[8];
    const float* al2 = (const float*)d_in[9];
    const float* ar2 = (const float*)d_in[10];
    const float* b2  = (const float*)d_in[11];
    const float* Wfc = (const float*)d_in[12];
    const float* bfc = (const float*)d_in[13];

    const int N = in_sizes[0] / D;
    const int E = in_sizes[1];

    float *el, *er, *ebuf, *acc, *gcnt;
    __half *bufH, *bufB;
    int *cnt, *rowptr, *cursor, *colv;
    cudaGetSymbolAddress((void**)&bufH,   g_bufH);
    cudaGetSymbolAddress((void**)&bufB,   g_bufB);
    cudaGetSymbolAddress((void**)&el,     g_el);
    cudaGetSymbolAddress((void**)&er,     g_er);
    cudaGetSymbolAddress((void**)&ebuf,   g_e);
    cudaGetSymbolAddress((void**)&cnt,    g_cnt);
    cudaGetSymbolAddress((void**)&rowptr, g_rowptr);
    cudaGetSymbolAddress((void**)&cursor, g_cursor);
    cudaGetSymbolAddress((void**)&colv,   g_col);
    cudaGetSymbolAddress((void**)&acc,    g_acc);
    cudaGetSymbolAddress((void**)&gcnt,   g_gcnt);

    cudaFuncSetAttribute(gemm_hmma_kernel,
                         cudaFuncAttributeMaxDynamicSharedMemorySize, GEMM_SMEM);

    const int TPB = 256;
    const int eBlocks     = (E + TPB - 1) / TPB;
    const int nWarpBlocks = (N * 32 + TPB - 1) / TPB;
    const int gemmBlocks  = (N + 127) / 128;

    // ---- CSR build (shared by both layers) ----
    cudaMemsetAsync(cnt, 0, (size_t)N * sizeof(int), 0);
    hist_kernel<<<eBlocks, TPB>>>(dst, cnt, E);
    scan_kernel<<<1, 1024>>>(cnt, rowptr, cursor, N);
    scatter_kernel<<<eBlocks, TPB>>>(src, dst, cursor, colv, E);

    // ---- layer 1 ----
    gemm_hmma_kernel<<<gemmBlocks, 512, GEMM_SMEM>>>(h, nullptr, W1, nullptr, 0,
                                                     al1, ar1, bufH, el, er, N);
    agg_kernel<<<nWarpBlocks, TPB>>>(rowptr, colv, el, er, bufH, ebuf, bufB, N,
                                     0, nullptr, nullptr, nullptr, nullptr, nullptr);

    // ---- layer 2 (pool fused into agg) ----
    gemm_hmma_kernel<<<gemmBlocks, 512, GEMM_SMEM>>>(nullptr, bufB, W2, b1, 1,
                                                     al2, ar2, bufH, el, er, N);
    cudaMemsetAsync(acc, 0, NGRAPH * 2 * sizeof(float), 0);
    cudaMemsetAsync(gcnt, 0, NGRAPH * sizeof(float), 0);
    agg_kernel<<<nWarpBlocks, TPB>>>(rowptr, colv, el, er, bufH, ebuf, nullptr, N,
                                     1, b2, Wfc, gid, acc, gcnt);

    // ---- finalize ----
    finalize_kernel<<<1, 64>>>(acc, gcnt, bfc, (float*)d_out);
}

// round 16
// speedup vs baseline: 1.3027x; 1.3027x over previous
#include <cuda_runtime.h>
#include <cuda_fp16.h>
#include <math.h>

#define D       128
#define NMAX    100000
#define EMAX    1600000
#define NGRAPH  64
#define NEG_SLOPE 0.2f
#define AS      136   // smem row stride in halves (128 + 8 pad)
#define FULL    0xffffffffu

typedef unsigned int  u32;
typedef unsigned long long u64;

// ---------------- scratch (static device globals; no allocation) ------------
__device__ __half g_bufH[(size_t)NMAX * D];  // layer feat fp16 (25.6 MB)
__device__ __half g_bufB[(size_t)NMAX * D];  // agg output fp16 (25.6 MB)
__device__ float  g_el[NMAX];
__device__ float  g_er[NMAX];
__device__ float  g_e[EMAX];                 // per-edge scratch (deg>32 path)
__device__ int    g_cnt[NMAX];
__device__ int    g_rowptr[NMAX + 1];
__device__ int    g_cursor[NMAX];
__device__ int    g_col[EMAX];               // src ids sorted by dst
__device__ int    g_bsum[128];               // per-block partial sums for scan
__device__ float  g_acc[NGRAPH * 2];
__device__ float  g_gcnt[NGRAPH];

// ================= CSR build =================
__global__ void hist_kernel(const int* __restrict__ dst, int* __restrict__ cnt, int E) {
    int i = blockIdx.x * blockDim.x + threadIdx.x;
    if (i < E) atomicAdd(&cnt[dst[i]], 1);
}

// ---- coalesced 3-phase exclusive scan (replaces single-block scan) ----
// phase 1: per-block (1024 elements) sums
__global__ void scan_reduce_kernel(const int* __restrict__ cnt,
                                   int* __restrict__ bsum, int N) {
    __shared__ int ws[8];
    int t  = threadIdx.x;
    int i0 = blockIdx.x * 1024 + 4 * t;
    int4 v = make_int4(0, 0, 0, 0);
    if (i0 < N) v = *(const int4*)&cnt[i0];
    int s = v.x + v.y + v.z + v.w;
#pragma unroll
    for (int o = 16; o; o >>= 1) s += __shfl_xor_sync(FULL, s, o);
    if ((t & 31) == 0) ws[t >> 5] = s;
    __syncthreads();
    if (t < 32) {
        int x = (t < 8) ? ws[t] : 0;
#pragma unroll
        for (int o = 16; o; o >>= 1) x += __shfl_xor_sync(FULL, x, o);
        if (t == 0) bsum[blockIdx.x] = x;
    }
}

// phase 2: exclusive scan of <=128 block sums (single small block)
__global__ void scan_sums_kernel(int* __restrict__ bsum, int nb) {
    __shared__ int wt[4];
    int t = threadIdx.x;          // 128 threads
    int lane = t & 31, w = t >> 5;
    int v = (t < nb) ? bsum[t] : 0;
    int inc = v;
#pragma unroll
    for (int o = 1; o < 32; o <<= 1) {
        int u = __shfl_up_sync(FULL, inc, o);
        if (lane >= o) inc += u;
    }
    if (lane == 31) wt[w] = inc;
    __syncthreads();
    int off = 0;
#pragma unroll
    for (int i = 0; i < 4; i++) if (i < w) off += wt[i];
    if (t < nb) bsum[t] = off + inc - v;   // exclusive prefix
}

// phase 3: per-block scan + write rowptr/cursor (coalesced int4)
__global__ void scan_write_kernel(const int* __restrict__ cnt,
                                  const int* __restrict__ bsum,
                                  int* __restrict__ rowptr,
                                  int* __restrict__ cursor, int N, int E) {
    __shared__ int wt[8];
    int t  = threadIdx.x;
    int lane = t & 31, w = t >> 5;
    int i0 = blockIdx.x * 1024 + 4 * t;
    int4 v = make_int4(0, 0, 0, 0);
    if (i0 < N) v = *(const int4*)&cnt[i0];
    int local = v.x + v.y + v.z + v.w;
    int inc = local;
#pragma unroll
    for (int o = 1; o < 32; o <<= 1) {
        int u = __shfl_up_sync(FULL, inc, o);
        if (lane >= o) inc += u;
    }
    if (lane == 31) wt[w] = inc;
    __syncthreads();
    int woff = 0;
#pragma unroll
    for (int i = 0; i < 8; i++) if (i < w) woff += wt[i];
    int run = bsum[blockIdx.x] + woff + inc - local;
    if (i0 < N) {
        int r0 = run, r1 = r0 + v.x, r2 = r1 + v.y, r3 = r2 + v.z;
        int4 r = make_int4(r0, r1, r2, r3);
        *(int4*)&rowptr[i0] = r;
        *(int4*)&cursor[i0] = r;
    }
    if (blockIdx.x == 0 && t == 0) rowptr[N] = E;
}

__global__ void scatter_kernel(const int* __restrict__ src, const int* __restrict__ dst,
                               int* __restrict__ cursor, int* __restrict__ col, int E) {
    int i = blockIdx.x * blockDim.x + threadIdx.x;
    if (i < E) {
        int p = atomicAdd(&cursor[dst[i]], 1);
        col[p] = src[i];
    }
}

// ====== HMMA GEMM: outH = half(act(X) @ W); fused el/er epilogue ============
#define GEMM_SMEM (2 * 128 * AS * 2 + 2 * 4 * 128 * 4)

__global__ void __launch_bounds__(512, 1)
gemm_hmma_kernel(const float* __restrict__ Xf, const __half* __restrict__ Xh,
                 const float* __restrict__ W,
                 const float* __restrict__ preBias, int preRelu,
                 const float* __restrict__ al, const float* __restrict__ ar,
                 __half* __restrict__ outH, float* __restrict__ el,
                 float* __restrict__ er, int N) {
    extern __shared__ char smraw[];
    __half* As = (__half*)smraw;                    // [128][AS]
    __half* Bs = As + 128 * AS;                     // [128][AS]
    float* redEl = (float*)(Bs + 128 * AS);         // [4][128]
    float* redEr = redEl + 4 * 128;                 // [4][128]

    const int tx   = threadIdx.x;
    const int lane = tx & 31;
    const int warp = tx >> 5;
    const int row0 = blockIdx.x * 128;

    // ---- stage W -> Bs (fp32 -> fp16) ----
    {
        int k  = tx >> 2;
        int n0 = (tx & 3) * 32;
        const float* wr_ = W + k * D + n0;
#pragma unroll
        for (int j = 0; j < 32; j += 8) {
            float4 v0 = *(const float4*)&wr_[j];
            float4 v1 = *(const float4*)&wr_[j + 4];
            __half2 h0 = __floats2half2_rn(v0.x, v0.y);
            __half2 h1 = __floats2half2_rn(v0.z, v0.w);
            __half2 h2 = __floats2half2_rn(v1.x, v1.y);
            __half2 h3 = __floats2half2_rn(v1.z, v1.w);
            uint4 u = make_uint4(*(u32*)&h0, *(u32*)&h1, *(u32*)&h2, *(u32*)&h3);
            *(uint4*)&Bs[k * AS + n0 + j] = u;
        }
    }

    // ---- stage X -> As ----
    {
        int r    = tx >> 2;
        int c0   = (tx & 3) * 32;
        int grow = row0 + r;
        if (grow < N) {
            if (Xf) {
                const float* xr_ = Xf + (size_t)grow * D + c0;
#pragma unroll
                for (int j = 0; j < 32; j += 8) {
                    float4 v0 = *(const float4*)&xr_[j];
                    float4 v1 = *(const float4*)&xr_[j + 4];
                    __half2 h0 = __floats2half2_rn(v0.x, v0.y);
                    __half2 h1 = __floats2half2_rn(v0.z, v0.w);
                    __half2 h2 = __floats2half2_rn(v1.x, v1.y);
                    __half2 h3 = __floats2half2_rn(v1.z, v1.w);
                    uint4 u = make_uint4(*(u32*)&h0, *(u32*)&h1, *(u32*)&h2, *(u32*)&h3);
                    *(uint4*)&As[r * AS + c0 + j] = u;
                }
            } else {
                const __half* xr_ = Xh + (size_t)grow * D + c0;
#pragma unroll
                for (int j = 0; j < 32; j += 8) {
                    uint4 raw = *(const uint4*)&xr_[j];
                    if (preRelu) {
                        const float* bb = preBias + c0 + j;
                        float2 f0 = __half22float2(*(__half2*)&raw.x);
                        float2 f1 = __half22float2(*(__half2*)&raw.y);
                        float2 f2 = __half22float2(*(__half2*)&raw.z);
                        float2 f3 = __half22float2(*(__half2*)&raw.w);
                        f0.x = fmaxf(f0.x + bb[0], 0.f); f0.y = fmaxf(f0.y + bb[1], 0.f);
                        f1.x = fmaxf(f1.x + bb[2], 0.f); f1.y = fmaxf(f1.y + bb[3], 0.f);
                        f2.x = fmaxf(f2.x + bb[4], 0.f); f2.y = fmaxf(f2.y + bb[5], 0.f);
                        f3.x = fmaxf(f3.x + bb[6], 0.f); f3.y = fmaxf(f3.y + bb[7], 0.f);
                        __half2 h0 = __floats2half2_rn(f0.x, f0.y);
                        __half2 h1 = __floats2half2_rn(f1.x, f1.y);
                        __half2 h2 = __floats2half2_rn(f2.x, f2.y);
                        __half2 h3 = __floats2half2_rn(f3.x, f3.y);
                        raw = make_uint4(*(u32*)&h0, *(u32*)&h1, *(u32*)&h2, *(u32*)&h3);
                    }
                    *(uint4*)&As[r * AS + c0 + j] = raw;
                }
            }
        } else {
#pragma unroll
            for (int j = 0; j < 32; j += 8)
                *(uint4*)&As[r * AS + c0 + j] = make_uint4(0, 0, 0, 0);
        }
    }
    __syncthreads();

    // ---- mainloop ----
    const int wr = warp >> 2;
    const int wc = warp & 3;
    float acc[2][4][4];
#pragma unroll
    for (int a = 0; a < 2; a++)
#pragma unroll
        for (int n = 0; n < 4; n++)
#pragma unroll
            for (int i = 0; i < 4; i++) acc[a][n][i] = 0.f;

    const u32 as_base = (u32)__cvta_generic_to_shared(As);
    const u32 bs_base = (u32)__cvta_generic_to_shared(Bs);
    const int g  = lane >> 3;
    const int gi = lane & 7;

#pragma unroll
    for (int ks = 0; ks < 8; ks++) {
        const int k0 = ks * 16;
        u32 afr[2][4];
#pragma unroll
        for (int at = 0; at < 2; at++) {
            int arow = wr * 32 + at * 16 + gi + (g & 1) * 8;
            int acol = k0 + (g >> 1) * 8;
            u32 addr = as_base + (arow * AS + acol) * 2;
            asm volatile("ldmatrix.sync.aligned.m8n8.x4.shared.b16 {%0,%1,%2,%3}, [%4];"
                         : "=r"(afr[at][0]), "=r"(afr[at][1]),
                           "=r"(afr[at][2]), "=r"(afr[at][3]) : "r"(addr));
        }
        u32 bfr[4][2];
#pragma unroll
        for (int h = 0; h < 2; h++) {
            int krow = k0 + gi + (g & 1) * 8;
            int ncol = wc * 32 + h * 16 + (g >> 1) * 8;
            u32 addr = bs_base + (krow * AS + ncol) * 2;
            u32 r0, r1, r2, r3;
            asm volatile("ldmatrix.sync.aligned.m8n8.x4.trans.shared.b16 {%0,%1,%2,%3}, [%4];"
                         : "=r"(r0), "=r"(r1), "=r"(r2), "=r"(r3) : "r"(addr));
            bfr[h * 2][0] = r0;     bfr[h * 2][1] = r1;
            bfr[h * 2 + 1][0] = r2; bfr[h * 2 + 1][1] = r3;
        }
#pragma unroll
        for (int at = 0; at < 2; at++)
#pragma unroll
            for (int nt = 0; nt < 4; nt++) {
                asm volatile(
                    "mma.sync.aligned.m16n8k16.row.col.f32.f16.f16.f32 "
                    "{%0,%1,%2,%3}, {%4,%5,%6,%7}, {%8,%9}, {%0,%1,%2,%3};"
                    : "+f"(acc[at][nt][0]), "+f"(acc[at][nt][1]),
                      "+f"(acc[at][nt][2]), "+f"(acc[at][nt][3])
                    : "r"(afr[at][0]), "r"(afr[at][1]), "r"(afr[at][2]), "r"(afr[at][3]),
                      "r"(bfr[nt][0]), "r"(bfr[nt][1]));
            }
    }

    // ---- epilogue ----
#pragma unroll
    for (int at = 0; at < 2; at++) {
        int r_lo = wr * 32 + at * 16 + (lane >> 2);
        int r_hi = r_lo + 8;
        float pll = 0.f, prl = 0.f, plh = 0.f, prh = 0.f;
#pragma unroll
        for (int nt = 0; nt < 4; nt++) {
            int colc = wc * 32 + nt * 8 + 2 * (lane & 3);
            float c0 = acc[at][nt][0], c1 = acc[at][nt][1];
            float c2 = acc[at][nt][2], c3 = acc[at][nt][3];
            float a0 = al[colc], a1 = al[colc + 1];
            float b0 = ar[colc], b1 = ar[colc + 1];
            pll += c0 * a0 + c1 * a1;  prl += c0 * b0 + c1 * b1;
            plh += c2 * a0 + c3 * a1;  prh += c2 * b0 + c3 * b1;
            if (row0 + r_lo < N) {
                __half2 h = __floats2half2_rn(c0, c1);
                *(__half2*)&outH[(size_t)(row0 + r_lo) * D + colc] = h;
            }
            if (row0 + r_hi < N) {
                __half2 h = __floats2half2_rn(c2, c3);
                *(__half2*)&outH[(size_t)(row0 + r_hi) * D + colc] = h;
            }
        }
#pragma unroll
        for (int o = 1; o <= 2; o <<= 1) {
            pll += __shfl_xor_sync(FULL, pll, o);
            prl += __shfl_xor_sync(FULL, prl, o);
            plh += __shfl_xor_sync(FULL, plh, o);
            prh += __shfl_xor_sync(FULL, prh, o);
        }
        if ((lane & 3) == 0) {
            redEl[wc * 128 + r_lo] = pll;  redEr[wc * 128 + r_lo] = prl;
            redEl[wc * 128 + r_hi] = plh;  redEr[wc * 128 + r_hi] = prh;
        }
    }
    __syncthreads();
    if (tx < 128 && row0 + tx < N) {
        float sl = redEl[tx] + redEl[128 + tx] + redEl[256 + tx] + redEl[384 + tx];
        float sr = redEr[tx] + redEr[128 + tx] + redEr[256 + tx] + redEr[384 + tx];
        el[row0 + tx] = sl;
        er[row0 + tx] = sr;
    }
}

// ========== fused per-dst edge softmax + aggregation (warp per dst) =========
__device__ __forceinline__ void fma_half8(float& a0, float& a1, float& a2, float& a3,
                                          float w, uint2 u) {
    float2 f0 = __half22float2(*reinterpret_cast<__half2*>(&u.x));
    float2 f1 = __half22float2(*reinterpret_cast<__half2*>(&u.y));
    a0 = fmaf(w, f0.x, a0); a1 = fmaf(w, f0.y, a1);
    a2 = fmaf(w, f1.x, a2); a3 = fmaf(w, f1.y, a3);
}

__global__ void agg_kernel(const int* __restrict__ rowptr, const int* __restrict__ col,
                           const float* __restrict__ el, const float* __restrict__ er,
                           const __half* __restrict__ feat, float* __restrict__ ebuf,
                           __half* __restrict__ out, int N, int doPool,
                           const float* __restrict__ b2, const float* __restrict__ Wfc,
                           const int* __restrict__ gid,
                           float* __restrict__ acc, float* __restrict__ gcnt) {
    int node = (blockIdx.x * blockDim.x + threadIdx.x) >> 5;
    int lane = threadIdx.x & 31;
    if (node >= N) return;
    int beg = rowptr[node], end = rowptr[node + 1];
    int deg = end - beg;
    float a0 = 0.f, a1 = 0.f, a2 = 0.f, a3 = 0.f;

    if (deg > 0) {
        float erd = er[node];
        if (deg <= 32) {
            int   myi = 0;
            float v = -INFINITY;
            if (lane < deg) {
                myi = col[beg + lane];
                float t = el[myi] + erd;
                v = t > 0.f ? t : NEG_SLOPE * t;
            }
            float mx = v;
#pragma unroll
            for (int o = 16; o; o >>= 1)
                mx = fmaxf(mx, __shfl_xor_sync(FULL, mx, o));
            float mye = (lane < deg) ? __expf(v - mx) : 0.f;
            float s = mye;
#pragma unroll
            for (int o = 16; o; o >>= 1)
                s += __shfl_xor_sync(FULL, s, o);
            float inv = 1.0f / s;
            int j = 0;
            for (; j + 7 < deg; j += 8) {
                int si[8]; float wi[8]; uint2 u[8];
#pragma unroll
                for (int t = 0; t < 8; t++) {
                    si[t] = __shfl_sync(FULL, myi, j + t);
                    wi[t] = __shfl_sync(FULL, mye, j + t) * inv;
                }
#pragma unroll
                for (int t = 0; t < 8; t++)
                    u[t] = *(const uint2*)(feat + (size_t)si[t] * D + lane * 4);
#pragma unroll
                for (int t = 0; t < 8; t++)
                    fma_half8(a0, a1, a2, a3, wi[t], u[t]);
            }
            for (; j + 3 < deg; j += 4) {
                int si[4]; float wi[4]; uint2 u[4];
#pragma unroll
                for (int t = 0; t < 4; t++) {
                    si[t] = __shfl_sync(FULL, myi, j + t);
                    wi[t] = __shfl_sync(FULL, mye, j + t) * inv;
                }
#pragma unroll
                for (int t = 0; t < 4; t++)
                    u[t] = *(const uint2*)(feat + (size_t)si[t] * D + lane * 4);
#pragma unroll
                for (int t = 0; t < 4; t++)
                    fma_half8(a0, a1, a2, a3, wi[t], u[t]);
            }
            for (; j < deg; j++) {
                int   sA = __shfl_sync(FULL, myi, j);
                float wA = __shfl_sync(FULL, mye, j) * inv;
                uint2 uA = *(const uint2*)(feat + (size_t)sA * D + lane * 4);
                fma_half8(a0, a1, a2, a3, wA, uA);
            }
        } else {
            float mx = -INFINITY;
            for (int i = beg + lane; i < end; i += 32) {
                float v = el[col[i]] + erd;
                v = v > 0.f ? v : NEG_SLOPE * v;
                ebuf[i] = v;
                mx = fmaxf(mx, v);
            }
#pragma unroll
            for (int o = 16; o; o >>= 1)
                mx = fmaxf(mx, __shfl_xor_sync(FULL, mx, o));
            float s = 0.f;
            for (int i = beg + lane; i < end; i += 32) {
                float ex = __expf(ebuf[i] - mx);
                ebuf[i] = ex;
                s += ex;
            }
#pragma unroll
            for (int o = 16; o; o >>= 1)
                s += __shfl_xor_sync(FULL, s, o);
            float inv = 1.0f / s;
            for (int base = beg; base < end; base += 32) {
                int rem = end - base;
                int cnt = rem < 32 ? rem : 32;
                int mi = 0; float me = 0.f;
                if (lane < cnt) { mi = col[base + lane]; me = ebuf[base + lane]; }
                int j = 0;
                for (; j + 7 < cnt; j += 8) {
                    int si[8]; float wi[8]; uint2 u[8];
#pragma unroll
                    for (int t = 0; t < 8; t++) {
                        si[t] = __shfl_sync(FULL, mi, j + t);
                        wi[t] = __shfl_sync(FULL, me, j + t) * inv;
                    }
#pragma unroll
                    for (int t = 0; t < 8; t++)
                        u[t] = *(const uint2*)(feat + (size_t)si[t] * D + lane * 4);
#pragma unroll
                    for (int t = 0; t < 8; t++)
                        fma_half8(a0, a1, a2, a3, wi[t], u[t]);
                }
                for (; j < cnt; j++) {
                    int   sA = __shfl_sync(FULL, mi, j);
                    float wA = __shfl_sync(FULL, me, j) * inv;
                    uint2 uA = *(const uint2*)(feat + (size_t)sA * D + lane * 4);
                    fma_half8(a0, a1, a2, a3, wA, uA);
                }
            }
        }
    }

    if (!doPool) {
        __half2 h01 = __floats2half2_rn(a0, a1);
        __half2 h23 = __floats2half2_rn(a2, a3);
        uint2 u; u.x = *(u32*)&h01; u.y = *(u32*)&h23;
        *(uint2*)&out[(size_t)node * D + lane * 4] = u;
    } else {
        float4 b = *(const float4*)&b2[lane * 4];
        float x0 = fmaxf(a0 + b.x, 0.f);
        float x1 = fmaxf(a1 + b.y, 0.f);
        float x2 = fmaxf(a2 + b.z, 0.f);
        float x3 = fmaxf(a3 + b.w, 0.f);
        float4 w01 = *(const float4*)&Wfc[lane * 8];
        float4 w23 = *(const float4*)&Wfc[lane * 8 + 4];
        float d0 = x0 * w01.x + x1 * w01.z + x2 * w23.x + x3 * w23.z;
        float d1 = x0 * w01.y + x1 * w01.w + x2 * w23.y + x3 * w23.w;
#pragma unroll
        for (int o = 16; o; o >>= 1) {
            d0 += __shfl_xor_sync(FULL, d0, o);
            d1 += __shfl_xor_sync(FULL, d1, o);
        }
        if (lane == 0) {
            int g = gid[node];
            atomicAdd(&acc[g * 2 + 0], d0);
            atomicAdd(&acc[g * 2 + 1], d1);
            atomicAdd(&gcnt[g], 1.f);
        }
    }
}

// ========== finalize: mean, +bfc, log_softmax ==========
__global__ void finalize_kernel(const float* __restrict__ acc,
                                const float* __restrict__ cnt,
                                const float* __restrict__ bfc,
                                float* __restrict__ out) {
    int g = threadIdx.x;
    if (g >= NGRAPH) return;
    float c  = fmaxf(cnt[g], 1.f);
    float l0 = acc[g * 2 + 0] / c + bfc[0];
    float l1 = acc[g * 2 + 1] / c + bfc[1];
    float mx  = fmaxf(l0, l1);
    float lse = mx + logf(expf(l0 - mx) + expf(l1 - mx));
    out[g * 2 + 0] = l0 - lse;
    out[g * 2 + 1] = l1 - lse;
}

// ================= launch =================
extern "C" void kernel_launch(void* const* d_in, const int* in_sizes, int n_in,
                              void* d_out, int out_size) {
    const float* h   = (const float*)d_in[0];
    const int*   src = (const int*)d_in[1];
    const int*   dst = (const int*)d_in[2];
    const int*   gid = (const int*)d_in[3];
    const float* W1  = (const float*)d_in[4];
    const float* al1 = (const float*)d_in[5];
    const float* ar1 = (const float*)d_in[6];
    const float* b1  = (const float*)d_in[7];
    const float* W2  = (const float*)d_in[8];
    const float* al2 = (const float*)d_in[9];
    const float* ar2 = (const float*)d_in[10];
    const float* b2  = (const float*)d_in[11];
    const float* Wfc = (const float*)d_in[12];
    const float* bfc = (const float*)d_in[13];

    const int N = in_sizes[0] / D;
    const int E = in_sizes[1];

    float *el, *er, *ebuf, *acc, *gcnt;
    __half *bufH, *bufB;
    int *cnt, *rowptr, *cursor, *colv, *bsum;
    cudaGetSymbolAddress((void**)&bufH,   g_bufH);
    cudaGetSymbolAddress((void**)&bufB,   g_bufB);
    cudaGetSymbolAddress((void**)&el,     g_el);
    cudaGetSymbolAddress((void**)&er,     g_er);
    cudaGetSymbolAddress((void**)&ebuf,   g_e);
    cudaGetSymbolAddress((void**)&cnt,    g_cnt);
    cudaGetSymbolAddress((void**)&rowptr, g_rowptr);
    cudaGetSymbolAddress((void**)&cursor, g_cursor);
    cudaGetSymbolAddress((void**)&colv,   g_col);
    cudaGetSymbolAddress((void**)&bsum,   g_bsum);
    cudaGetSymbolAddress((void**)&acc,    g_acc);
    cudaGetSymbolAddress((void**)&gcnt,   g_gcnt);

    cudaFuncSetAttribute(gemm_hmma_kernel,
                         cudaFuncAttributeMaxDynamicSharedMemorySize, GEMM_SMEM);

    const int TPB = 256;
    const int eBlocks     = (E + TPB - 1) / TPB;
    const int nWarpBlocks = (N * 32 + TPB - 1) / TPB;
    const int gemmBlocks  = (N + 127) / 128;
    const int scanBlocks  = (N + 1023) / 1024;     // <= 98 for N=100k

    // ---- CSR build (shared by both layers) ----
    cudaMemsetAsync(cnt, 0, (size_t)N * sizeof(int), 0);
    hist_kernel<<<eBlocks, TPB>>>(dst, cnt, E);
    scan_reduce_kernel<<<scanBlocks, TPB>>>(cnt, bsum, N);
    scan_sums_kernel<<<1, 128>>>(bsum, scanBlocks);
    scan_write_kernel<<<scanBlocks, TPB>>>(cnt, bsum, rowptr, cursor, N, E);
    scatter_kernel<<<eBlocks, TPB>>>(src, dst, cursor, colv, E);

    // ---- layer 1 ----
    gemm_hmma_kernel<<<gemmBlocks, 512, GEMM_SMEM>>>(h, nullptr, W1, nullptr, 0,
                                                     al1, ar1, bufH, el, er, N);
    agg_kernel<<<nWarpBlocks, TPB>>>(rowptr, colv, el, er, bufH, ebuf, bufB, N,
                                     0, nullptr, nullptr, nullptr, nullptr, nullptr);

    // ---- layer 2 (pool fused into agg) ----
    gemm_hmma_kernel<<<gemmBlocks, 512, GEMM_SMEM>>>(nullptr, bufB, W2, b1, 1,
                                                     al2, ar2, bufH, el, er, N);
    cudaMemsetAsync(acc, 0, NGRAPH * 2 * sizeof(float), 0);
    cudaMemsetAsync(gcnt, 0, NGRAPH * sizeof(float), 0);
    agg_kernel<<<nWarpBlocks, TPB>>>(rowptr, colv, el, er, bufH, ebuf, nullptr, N,
                                     1, b2, Wfc, gid, acc, gcnt);

    // ---- finalize ----
    finalize_kernel<<<1, 64>>>(acc, gcnt, bfc, (float*)d_out);
}